// round 6
// baseline (speedup 1.0000x reference)
#include <cuda_runtime.h>
#include <cstdint>

// CarryLSTMModel: B=8192, T=1024, D=16, H=16 (4H=64 gates, order i,f,g,o)
// 16 lanes per batch element, 4 batch elements per warp (2 per lane).
// Lane j (=lane&15) owns gate columns {j, j+16, j+32, j+48} for both elements.
// Weights register-resident as f32x2 pairs over adjacent k (fma.rn.f32x2).
// h-exchange via double-buffered SMEM (2 STS + 8 broadcast LDS.128 + 1 syncwarp
// per warp-step) instead of 32 SHFLs -> ~10x less MIO pressure.
// Activations via MUFU.TANH: sig(z) = 0.5 + 0.5*tanh(z/2) (weights pre-scaled).

#define NB 8192
#define NT 1024
#define ND 16
#define NG 64

typedef unsigned long long u64;
typedef unsigned int u32;

__device__ __forceinline__ u64 pack2(float lo, float hi) {
    u64 r;
    asm("mov.b64 %0, {%1, %2};" : "=l"(r) : "r"(__float_as_uint(lo)), "r"(__float_as_uint(hi)));
    return r;
}
__device__ __forceinline__ void unpack2(u64 v, float& lo, float& hi) {
    u32 a, b;
    asm("mov.b64 {%0, %1}, %2;" : "=r"(a), "=r"(b) : "l"(v));
    lo = __uint_as_float(a);
    hi = __uint_as_float(b);
}
__device__ __forceinline__ u64 ffma2(u64 a, u64 b, u64 c) {
    u64 d;
    asm("fma.rn.f32x2 %0, %1, %2, %3;" : "=l"(d) : "l"(a), "l"(b), "l"(c));
    return d;
}
__device__ __forceinline__ u64 fadd2(u64 a, u64 b) {
    u64 d;
    asm("add.rn.f32x2 %0, %1, %2;" : "=l"(d) : "l"(a), "l"(b));
    return d;
}
__device__ __forceinline__ float tanhap(float x) {
    float r; asm("tanh.approx.f32 %0, %1;" : "=f"(r) : "f"(x)); return r;
}
__device__ __forceinline__ float ex2f(float x) {
    float r; asm("ex2.approx.f32 %0, %1;" : "=f"(r) : "f"(x)); return r;
}
__device__ __forceinline__ float rcpf(float x) {
    float r; asm("rcp.approx.f32 %0, %1;" : "=f"(r) : "f"(x)); return r;
}

__global__ __launch_bounds__(128, 2)
void lstm_fused_kernel(const float* __restrict__ x,
                       const float* __restrict__ Wi,
                       const float* __restrict__ Wh,
                       const float* __restrict__ bias,
                       const float* __restrict__ Wd,
                       const float* __restrict__ bd,
                       float* __restrict__ out)
{
    // double-buffered h: [buf][warp][elem-in-warp][16]
    __shared__ float hbuf[2][4][4][16];

    const int wib  = threadIdx.x >> 5;
    const int lane = threadIdx.x & 31;
    const int half = lane >> 4;          // which half of the warp
    const int j    = lane & 15;          // gate index owned by this lane
    const int base = blockIdx.x * 16 + wib * 4 + half * 2;  // this lane's 2 elements
    const int r0 = half * 2, r1 = half * 2 + 1;  // elem rows in hbuf

    // sig(z) = 0.5 + 0.5*tanh(z/2): accumulate z/2 directly for i/f/o.
    const float sI = 0.5f, sF = 0.5f, sG = 1.0f, sO = 0.5f;
    const int ci = j, cf = j + 16, cg = j + 32, co = j + 48;

    // weights as f32x2 pairs over adjacent k: [0..7]=Wi pairs, [8..15]=Wh pairs
    u64 wI[16], wF[16], wG[16], wO[16];
#pragma unroll
    for (int m = 0; m < 8; ++m) {
        wI[m]     = pack2(Wi[(2*m) * NG + ci] * sI, Wi[(2*m+1) * NG + ci] * sI);
        wF[m]     = pack2(Wi[(2*m) * NG + cf] * sF, Wi[(2*m+1) * NG + cf] * sF);
        wG[m]     = pack2(Wi[(2*m) * NG + cg] * sG, Wi[(2*m+1) * NG + cg] * sG);
        wO[m]     = pack2(Wi[(2*m) * NG + co] * sO, Wi[(2*m+1) * NG + co] * sO);
        wI[8 + m] = pack2(Wh[(2*m) * NG + ci] * sI, Wh[(2*m+1) * NG + ci] * sI);
        wF[8 + m] = pack2(Wh[(2*m) * NG + cf] * sF, Wh[(2*m+1) * NG + cf] * sF);
        wG[8 + m] = pack2(Wh[(2*m) * NG + cg] * sG, Wh[(2*m+1) * NG + cg] * sG);
        wO[8 + m] = pack2(Wh[(2*m) * NG + co] * sO, Wh[(2*m+1) * NG + co] * sO);
    }
    const u64 bI2 = pack2(bias[ci] * sI, 0.f);
    const u64 bF2 = pack2(bias[cf] * sF, 0.f);
    const u64 bG2 = pack2(bias[cg] * sG, 0.f);
    const u64 bO2 = pack2(bias[co] * sO, 0.f);

    const float4* xp0 = (const float4*)(x + (size_t)(base + 0) * (NT * ND));
    const float4* xp1 = (const float4*)(x + (size_t)(base + 1) * (NT * ND));

    float c0 = 0.f, c1 = 0.f;

    // zero-init read buffer 0
    hbuf[0][wib][r0][j] = 0.f;
    hbuf[0][wib][r1][j] = 0.f;
    __syncwarp();

    float4 a0 = xp0[0], a1 = xp0[1], a2 = xp0[2], a3 = xp0[3];   // elem0 cur x
    float4 e0 = xp1[0], e1 = xp1[1], e2 = xp1[2], e3 = xp1[3];   // elem1 cur x

    // step: read h from hbuf[p], write new h to hbuf[p^1], then syncwarp.
    auto step = [&](int p,
                    const float4& u0, const float4& u1, const float4& u2, const float4& u3,
                    const float4& v0, const float4& v1, const float4& v2, const float4& v3) {
        const float4* rp0 = (const float4*)&hbuf[p][wib][r0][0];
        const float4* rp1 = (const float4*)&hbuf[p][wib][r1][0];
        float4 H00 = rp0[0], H01 = rp0[1], H02 = rp0[2], H03 = rp0[3];
        float4 H10 = rp1[0], H11 = rp1[1], H12 = rp1[2], H13 = rp1[3];

        u64 hp0[8], hp1[8];
        hp0[0] = pack2(H00.x, H00.y); hp0[1] = pack2(H00.z, H00.w);
        hp0[2] = pack2(H01.x, H01.y); hp0[3] = pack2(H01.z, H01.w);
        hp0[4] = pack2(H02.x, H02.y); hp0[5] = pack2(H02.z, H02.w);
        hp0[6] = pack2(H03.x, H03.y); hp0[7] = pack2(H03.z, H03.w);
        hp1[0] = pack2(H10.x, H10.y); hp1[1] = pack2(H10.z, H10.w);
        hp1[2] = pack2(H11.x, H11.y); hp1[3] = pack2(H11.z, H11.w);
        hp1[4] = pack2(H12.x, H12.y); hp1[5] = pack2(H12.z, H12.w);
        hp1[6] = pack2(H13.x, H13.y); hp1[7] = pack2(H13.z, H13.w);

        u64 xq0[8], xq1[8];
        xq0[0] = pack2(u0.x, u0.y); xq0[1] = pack2(u0.z, u0.w);
        xq0[2] = pack2(u1.x, u1.y); xq0[3] = pack2(u1.z, u1.w);
        xq0[4] = pack2(u2.x, u2.y); xq0[5] = pack2(u2.z, u2.w);
        xq0[6] = pack2(u3.x, u3.y); xq0[7] = pack2(u3.z, u3.w);
        xq1[0] = pack2(v0.x, v0.y); xq1[1] = pack2(v0.z, v0.w);
        xq1[2] = pack2(v1.x, v1.y); xq1[3] = pack2(v1.z, v1.w);
        xq1[4] = pack2(v2.x, v2.y); xq1[5] = pack2(v2.z, v2.w);
        xq1[6] = pack2(v3.x, v3.y); xq1[7] = pack2(v3.z, v3.w);

        // x-chains (carry bias) — independent of h, proceed during LDS window
        u64 aI0 = bI2, aF0 = bF2, aG0 = bG2, aO0 = bO2;
        u64 aI1 = bI2, aF1 = bF2, aG1 = bG2, aO1 = bO2;
        // h-chains — separate 8-deep chains, merged after
        u64 hI0 = 0, hF0 = 0, hG0 = 0, hO0 = 0;
        u64 hI1 = 0, hF1 = 0, hG1 = 0, hO1 = 0;
#pragma unroll
        for (int m = 0; m < 8; ++m) {
            aI0 = ffma2(xq0[m], wI[m], aI0);
            aF0 = ffma2(xq0[m], wF[m], aF0);
            aG0 = ffma2(xq0[m], wG[m], aG0);
            aO0 = ffma2(xq0[m], wO[m], aO0);
            aI1 = ffma2(xq1[m], wI[m], aI1);
            aF1 = ffma2(xq1[m], wF[m], aF1);
            aG1 = ffma2(xq1[m], wG[m], aG1);
            aO1 = ffma2(xq1[m], wO[m], aO1);
        }
#pragma unroll
        for (int m = 0; m < 8; ++m) {
            hI0 = ffma2(hp0[m], wI[8 + m], hI0);
            hF0 = ffma2(hp0[m], wF[8 + m], hF0);
            hG0 = ffma2(hp0[m], wG[8 + m], hG0);
            hO0 = ffma2(hp0[m], wO[8 + m], hO0);
            hI1 = ffma2(hp1[m], wI[8 + m], hI1);
            hF1 = ffma2(hp1[m], wF[8 + m], hF1);
            hG1 = ffma2(hp1[m], wG[8 + m], hG1);
            hO1 = ffma2(hp1[m], wO[8 + m], hO1);
        }
        aI0 = fadd2(aI0, hI0); aF0 = fadd2(aF0, hF0);
        aG0 = fadd2(aG0, hG0); aO0 = fadd2(aO0, hO0);
        aI1 = fadd2(aI1, hI1); aF1 = fadd2(aF1, hF1);
        aG1 = fadd2(aG1, hG1); aO1 = fadd2(aO1, hO1);

        float lo, hi, zI, zF, zG, zO, h0n, h1n;
        unpack2(aI0, lo, hi); zI = lo + hi;
        unpack2(aF0, lo, hi); zF = lo + hi;
        unpack2(aG0, lo, hi); zG = lo + hi;
        unpack2(aO0, lo, hi); zO = lo + hi;
        {
            float vI = fmaf(0.5f, tanhap(zI), 0.5f);
            float vF = fmaf(0.5f, tanhap(zF), 0.5f);
            float vG = tanhap(zG);
            float vO = fmaf(0.5f, tanhap(zO), 0.5f);
            c0 = fmaf(vF, c0, vI * vG);
            h0n = vO * tanhap(c0);
        }
        unpack2(aI1, lo, hi); zI = lo + hi;
        unpack2(aF1, lo, hi); zF = lo + hi;
        unpack2(aG1, lo, hi); zG = lo + hi;
        unpack2(aO1, lo, hi); zO = lo + hi;
        {
            float vI = fmaf(0.5f, tanhap(zI), 0.5f);
            float vF = fmaf(0.5f, tanhap(zF), 0.5f);
            float vG = tanhap(zG);
            float vO = fmaf(0.5f, tanhap(zO), 0.5f);
            c1 = fmaf(vF, c1, vI * vG);
            h1n = vO * tanhap(c1);
        }

        hbuf[p ^ 1][wib][r0][j] = h0n;
        hbuf[p ^ 1][wib][r1][j] = h1n;
        __syncwarp();
    };

#pragma unroll 1
    for (int t = 0; t < NT; t += 2) {
        // prefetch t+1 for both elements while computing t (reads buf 0)
        const float4* q0 = xp0 + (t + 1) * 4;
        const float4* q1 = xp1 + (t + 1) * 4;
        float4 n0 = q0[0], n1 = q0[1], n2 = q0[2], n3 = q0[3];
        float4 m0 = q1[0], m1 = q1[1], m2 = q1[2], m3 = q1[3];
        step(0, a0, a1, a2, a3, e0, e1, e2, e3);

        // prefetch t+2 (clamped) while computing t+1 (reads buf 1)
        int tp = (t + 2 < NT) ? (t + 2) : (NT - 1);
        const float4* p0 = xp0 + tp * 4;
        const float4* p1 = xp1 + tp * 4;
        a0 = p0[0]; a1 = p0[1]; a2 = p0[2]; a3 = p0[3];
        e0 = p1[0]; e1 = p1[1]; e2 = p1[2]; e3 = p1[3];
        step(1, n0, n1, n2, n3, m0, m1, m2, m3);
    }

    // head: logits = c_T @ Wd + bd, softmax over 2 classes.
    const float L2E = 1.44269504088896340736f;
    const float wd0 = Wd[2 * j], wd1 = Wd[2 * j + 1];
    float p00 = c0 * wd0, p01 = c0 * wd1;
    float p10 = c1 * wd0, p11 = c1 * wd1;
#pragma unroll
    for (int off = 8; off; off >>= 1) {
        p00 += __shfl_xor_sync(0xffffffffu, p00, off, 16);
        p01 += __shfl_xor_sync(0xffffffffu, p01, off, 16);
        p10 += __shfl_xor_sync(0xffffffffu, p10, off, 16);
        p11 += __shfl_xor_sync(0xffffffffu, p11, off, 16);
    }
    if (j == 0) {
        const float b0 = bd[0], b1 = bd[1];
        {
            float l0 = p00 + b0, l1 = p01 + b1;
            float mx = fmaxf(l0, l1);
            float q0v = ex2f((l0 - mx) * L2E);
            float q1v = ex2f((l1 - mx) * L2E);
            float inv = rcpf(q0v + q1v);
            out[2 * base]     = q0v * inv;
            out[2 * base + 1] = q1v * inv;
        }
        {
            float l0 = p10 + b0, l1 = p11 + b1;
            float mx = fmaxf(l0, l1);
            float q0v = ex2f((l0 - mx) * L2E);
            float q1v = ex2f((l1 - mx) * L2E);
            float inv = rcpf(q0v + q1v);
            out[2 * (base + 1)]     = q0v * inv;
            out[2 * (base + 1) + 1] = q1v * inv;
        }
    }
}

extern "C" void kernel_launch(void* const* d_in, const int* in_sizes, int n_in,
                              void* d_out, int out_size)
{
    const float* x  = (const float*)d_in[0];
    const float* Wi = (const float*)d_in[1];
    const float* Wh = (const float*)d_in[2];
    const float* b  = (const float*)d_in[3];
    const float* Wd = (const float*)d_in[4];
    const float* bd = (const float*)d_in[5];
    float* out = (float*)d_out;

    lstm_fused_kernel<<<NB / 16, 128>>>(x, Wi, Wh, b, Wd, bd, out);
}

// round 7
// speedup vs baseline: 1.0420x; 1.0420x over previous
#include <cuda_runtime.h>
#include <cstdint>

// CarryLSTMModel: B=8192, T=1024, D=16, H=16 (4H=64 gates, order i,f,g,o)
// Split-K layout: 1 warp = 2 batch elements (A, B).
//   lanes 0-15  (x-group): hold Wi weights for cols {j,j+16,j+32,j+48},
//                          compute x-partials of z for BOTH elements.
//   lanes 16-31 (h-group): hold Wh weights for the same cols,
//                          compute h-partials of z for BOTH elements.
// Same FFMA2 instructions serve both roles (per-lane weights/operands):
// weight registers drop 128 -> 64. One shfl_xor(16) per gate merges the
// partials AND redistributes: elem A's z lands on low lanes, elem B's on
// high lanes -> activations at full 32-lane density.
// x staged through smem via cp.async (no register prefetch buffers).
// h exchanged through double-buffered smem (1 STS + reads fused with x LDS).

#define NB 8192
#define NT 1024
#define ND 16
#define NG 64

typedef unsigned long long u64;
typedef unsigned int u32;

__device__ __forceinline__ u64 pack2(float lo, float hi) {
    u64 r;
    asm("mov.b64 %0, {%1, %2};" : "=l"(r) : "r"(__float_as_uint(lo)), "r"(__float_as_uint(hi)));
    return r;
}
__device__ __forceinline__ void unpack2(u64 v, float& lo, float& hi) {
    u32 a, b;
    asm("mov.b64 {%0, %1}, %2;" : "=r"(a), "=r"(b) : "l"(v));
    lo = __uint_as_float(a);
    hi = __uint_as_float(b);
}
__device__ __forceinline__ u64 ffma2(u64 a, u64 b, u64 c) {
    u64 d;
    asm("fma.rn.f32x2 %0, %1, %2, %3;" : "=l"(d) : "l"(a), "l"(b), "l"(c));
    return d;
}
__device__ __forceinline__ float tanhap(float x) {
    float r; asm("tanh.approx.f32 %0, %1;" : "=f"(r) : "f"(x)); return r;
}
__device__ __forceinline__ float ex2f(float x) {
    float r; asm("ex2.approx.f32 %0, %1;" : "=f"(r) : "f"(x)); return r;
}
__device__ __forceinline__ float rcpf(float x) {
    float r; asm("rcp.approx.f32 %0, %1;" : "=f"(r) : "f"(x)); return r;
}
__device__ __forceinline__ u32 smem_u32(const void* p) {
    return (u32)__cvta_generic_to_shared(p);
}

__global__ __launch_bounds__(128, 3)
void lstm_fused_kernel(const float* __restrict__ x,
                       const float* __restrict__ Wi,
                       const float* __restrict__ Wh,
                       const float* __restrict__ bias,
                       const float* __restrict__ Wd,
                       const float* __restrict__ bd,
                       float* __restrict__ out)
{
    // x staging: [buf][warp][elem(2)][k(16)]  = 2*4*2*16*4B = 1 KB
    __shared__ float xsm[2][4][2][16];
    // h state:   [buf][warp][0..15 = hA, 16..31 = hB]       = 1 KB
    __shared__ float hsm[2][4][32];

    const int wib  = threadIdx.x >> 5;
    const int lane = threadIdx.x & 31;
    const int half = lane >> 4;      // 0 = x-group, 1 = h-group
    const int j    = lane & 15;      // gate index / hidden index
    const int e0   = blockIdx.x * 8 + wib * 2;   // warp's element A; B = e0+1

    // sig(z) = 0.5 + 0.5*tanh(z/2): weights/bias pre-scaled so z is the tanh arg.
    const float sI = 0.5f, sF = 0.5f, sG = 1.0f, sO = 0.5f;
    const int ci = j, cf = j + 16, cg = j + 32, co = j + 48;

    // per-lane weight source: x-group reads Wi, h-group reads Wh (same cols)
    const float* Wsrc = (half == 0) ? Wi : Wh;
    u64 wI[8], wF[8], wG[8], wO[8];
#pragma unroll
    for (int m = 0; m < 8; ++m) {
        wI[m] = pack2(Wsrc[(2*m) * NG + ci] * sI, Wsrc[(2*m+1) * NG + ci] * sI);
        wF[m] = pack2(Wsrc[(2*m) * NG + cf] * sF, Wsrc[(2*m+1) * NG + cf] * sF);
        wG[m] = pack2(Wsrc[(2*m) * NG + cg] * sG, Wsrc[(2*m+1) * NG + cg] * sG);
        wO[m] = pack2(Wsrc[(2*m) * NG + co] * sO, Wsrc[(2*m+1) * NG + co] * sO);
    }
    // bias added exactly once per element: fold into x-group's accumulator init
    const u64 bI2 = pack2((half == 0) ? bias[ci] * sI : 0.f, 0.f);
    const u64 bF2 = pack2((half == 0) ? bias[cf] * sF : 0.f, 0.f);
    const u64 bG2 = pack2((half == 0) ? bias[cg] * sG : 0.f, 0.f);
    const u64 bO2 = pack2((half == 0) ? bias[co] * sO : 0.f, 0.f);

    // cp.async setup: lanes 0-7 fetch 8 x 16B = 2 elems x 16 floats per step
    const float* xsrc = x + (size_t)(e0 + ((lane >> 2) & 1)) * (NT * ND) + (lane & 3) * 4;
    const u32 xdst0 = smem_u32(&xsm[0][wib][(lane >> 2) & 1][(lane & 3) * 4]);
    const u32 xbufstride = 4 * 2 * 16 * 4;   // 512 B between buffers

    // per-lane smem read base: x-group reads xsm row, h-group reads hsm row
    const float4* dbase0 = (half == 0) ? (const float4*)&xsm[0][wib][0][0]
                                       : (const float4*)&hsm[0][wib][0];
    const float4* dbase1 = (half == 0) ? (const float4*)&xsm[1][wib][0][0]
                                       : (const float4*)&hsm[1][wib][0];

    // init h = 0 (buffer 0), prefetch x(t=0) into buffer 0
    hsm[0][wib][lane] = 0.f;
    if (lane < 8) {
        asm volatile("cp.async.ca.shared.global [%0], [%1], 16;"
                     :: "r"(xdst0), "l"(xsrc) : "memory");
    }
    asm volatile("cp.async.commit_group;" ::: "memory");

    float c = 0.f;   // cell state: elem A on low lanes, elem B on high lanes
    float hv = 0.f;  // hidden state, same split

#pragma unroll 1
    for (int t = 0; t < NT; ++t) {
        const int b  = t & 1;
        const int b1 = b ^ 1;

        // prefetch x(t+1) into the other buffer (clamped reload on last iter)
        {
            int t1 = (t + 1 < NT) ? (t + 1) : (NT - 1);
            if (lane < 8) {
                asm volatile("cp.async.ca.shared.global [%0], [%1], 16;"
                             :: "r"(xdst0 + (u32)(((t + 1) & 1) * xbufstride)),
                                "l"(xsrc + (size_t)t1 * ND) : "memory");
            }
            asm volatile("cp.async.commit_group;" ::: "memory");
        }
        // ensure x(t) landed; order h(t) writes vs reads warp-wide
        asm volatile("cp.async.wait_group 1;" ::: "memory");
        __syncwarp();

        // load this lane's operand stream: x-group gets x[16] of A then B,
        // h-group gets h[16] of A then B — same instruction slots.
        const float4* dp = b ? dbase1 : dbase0;
        float4 A0 = dp[0], A1 = dp[1], A2 = dp[2], A3 = dp[3];
        float4 B0 = dp[4], B1 = dp[5], B2 = dp[6], B3 = dp[7];

        u64 qA[8], qB[8];
        qA[0] = pack2(A0.x, A0.y); qA[1] = pack2(A0.z, A0.w);
        qA[2] = pack2(A1.x, A1.y); qA[3] = pack2(A1.z, A1.w);
        qA[4] = pack2(A2.x, A2.y); qA[5] = pack2(A2.z, A2.w);
        qA[6] = pack2(A3.x, A3.y); qA[7] = pack2(A3.z, A3.w);
        qB[0] = pack2(B0.x, B0.y); qB[1] = pack2(B0.z, B0.w);
        qB[2] = pack2(B1.x, B1.y); qB[3] = pack2(B1.z, B1.w);
        qB[4] = pack2(B2.x, B2.y); qB[5] = pack2(B2.z, B2.w);
        qB[6] = pack2(B3.x, B3.y); qB[7] = pack2(B3.z, B3.w);

        // partial z accumulation (x-part on low lanes, h-part on high lanes)
        u64 aI = bI2, aF = bF2, aG = bG2, aO = bO2;   // elem A
        u64 eI = bI2, eF = bF2, eG = bG2, eO = bO2;   // elem B
#pragma unroll
        for (int m = 0; m < 8; ++m) {
            aI = ffma2(qA[m], wI[m], aI);
            aF = ffma2(qA[m], wF[m], aF);
            aG = ffma2(qA[m], wG[m], aG);
            aO = ffma2(qA[m], wO[m], aO);
            eI = ffma2(qB[m], wI[m], eI);
            eF = ffma2(qB[m], wF[m], eF);
            eG = ffma2(qB[m], wG[m], eG);
            eO = ffma2(qB[m], wO[m], eO);
        }

        float lo, hi;
        float zIA, zFA, zGA, zOA, zIB, zFB, zGB, zOB;
        unpack2(aI, lo, hi); zIA = lo + hi;
        unpack2(aF, lo, hi); zFA = lo + hi;
        unpack2(aG, lo, hi); zGA = lo + hi;
        unpack2(aO, lo, hi); zOA = lo + hi;
        unpack2(eI, lo, hi); zIB = lo + hi;
        unpack2(eF, lo, hi); zFB = lo + hi;
        unpack2(eG, lo, hi); zGB = lo + hi;
        unpack2(eO, lo, hi); zOB = lo + hi;

        // combine halves + redistribute: low lanes end with elem A's z,
        // high lanes with elem B's z. Send the "other element's" partial.
        float sI_ = half ? zIA : zIB;
        float sF_ = half ? zFA : zFB;
        float sG_ = half ? zGA : zGB;
        float sO_ = half ? zOA : zOB;
        float rI = __shfl_xor_sync(0xffffffffu, sI_, 16);
        float rF = __shfl_xor_sync(0xffffffffu, sF_, 16);
        float rG = __shfl_xor_sync(0xffffffffu, sG_, 16);
        float rO = __shfl_xor_sync(0xffffffffu, sO_, 16);
        float zI = (half ? zIB : zIA) + rI;
        float zF = (half ? zFB : zFA) + rF;
        float zG = (half ? zGB : zGA) + rG;
        float zO = (half ? zOB : zOA) + rO;

        // activations at full lane density
        float vI = fmaf(0.5f, tanhap(zI), 0.5f);   // sig
        float vF = fmaf(0.5f, tanhap(zF), 0.5f);   // sig
        float vG = tanhap(zG);                     // tanh
        float vO = fmaf(0.5f, tanhap(zO), 0.5f);   // sig
        c  = fmaf(vF, c, vI * vG);
        hv = vO * tanhap(c);

        // publish h(t+1): [0..15]=hA[j], [16..31]=hB[j]
        hsm[b1][wib][lane] = hv;
    }

    // head: logits = c_T @ Wd + bd, softmax over 2 classes.
    // low lanes hold cA, high lanes cB — reduce each half independently.
    const float L2E = 1.44269504088896340736f;
    float p0 = c * Wd[2 * j];
    float p1 = c * Wd[2 * j + 1];
#pragma unroll
    for (int off = 8; off; off >>= 1) {
        p0 += __shfl_xor_sync(0xffffffffu, p0, off, 16);
        p1 += __shfl_xor_sync(0xffffffffu, p1, off, 16);
    }
    if (j == 0) {
        const int elem = e0 + half;
        float l0 = p0 + bd[0];
        float l1 = p1 + bd[1];
        float mx = fmaxf(l0, l1);
        float q0 = ex2f((l0 - mx) * L2E);
        float q1 = ex2f((l1 - mx) * L2E);
        float inv = rcpf(q0 + q1);
        out[2 * elem]     = q0 * inv;
        out[2 * elem + 1] = q1 * inv;
    }
}

extern "C" void kernel_launch(void* const* d_in, const int* in_sizes, int n_in,
                              void* d_out, int out_size)
{
    const float* x  = (const float*)d_in[0];
    const float* Wi = (const float*)d_in[1];
    const float* Wh = (const float*)d_in[2];
    const float* b  = (const float*)d_in[3];
    const float* Wd = (const float*)d_in[4];
    const float* bd = (const float*)d_in[5];
    float* out = (float*)d_out;

    lstm_fused_kernel<<<NB / 8, 128>>>(x, Wi, Wh, b, Wd, bd, out);
}